// round 2
// baseline (speedup 1.0000x reference)
#include <cuda_runtime.h>

// Problem constants
#define Hd   512
#define Bb   32
#define Ss   512
#define Wd   4
#define SPd  (Ss + 2*Wd)        // 520 padded seq length
#define CINd ((Wd+1)*Hd)        // 2560
#define MT   (Bb*Ss)            // 16384 rows
#define LLd  3

typedef unsigned long long ull;

// Scratch (static device arrays; no runtime allocation).
// Padded activation buffers double as the highway state: the highway input x
// for layer i lives in the interior of the (i+1)-parity padded buffer.
__device__ float g_pad_f[2][Bb * SPd * Hd];   // 2 x 34 MB
__device__ float g_pad_b[2][Bb * SPd * Hd];   // 2 x 34 MB
__device__ float g_tmp[MT * 2 * Hd];          // 67 MB highway proj scratch

// ---------------- packed fp32x2 helpers (sm_103a) ----------------
__device__ __forceinline__ ull f2_pack(float lo, float hi) {
    ull r; asm("mov.b64 %0, {%1, %2};" : "=l"(r) : "f"(lo), "f"(hi)); return r;
}
__device__ __forceinline__ void f2_unpack(ull v, float &lo, float &hi) {
    asm("mov.b64 {%0, %1}, %2;" : "=f"(lo), "=f"(hi) : "l"(v));
}
__device__ __forceinline__ ull f2_fma(ull a, ull b, ull c) {
    ull d; asm("fma.rn.f32x2 %0, %1, %2, %3;" : "=l"(d) : "l"(a), "l"(b), "l"(c));
    return d;
}

// Conv row mapping: logical row r (0..16383) -> padded-buffer row index
// (b*SP + t), expressed relative to an interior/base pointer. In floats.
__device__ __forceinline__ size_t crow(int r) {
    return (size_t)(r + ((r >> 9) << 3)) * Hd;
}

// ---------------- GEMM: C[M=16384, N] = epi(A @ W + bias) ----------------
// A rows are conv-mapped (overlapping windows / padded-interior rows).
// W is [K, N] row-major. CMAP: C rows conv-mapped with width 512; else plain ldc=N.
template<int K, bool CMAP, bool RELU>
__global__ __launch_bounds__(256, 2)
void gemm_k(const float* __restrict__ A, const float* __restrict__ W,
            const float* __restrict__ bias, float* __restrict__ C, int N)
{
    __shared__ __align__(16) float As[8][132];   // padded to kill STS conflicts
    __shared__ __align__(16) float Bs[8][128];

    const int tid = threadIdx.x;
    const int m0 = blockIdx.y << 7;
    const int n0 = blockIdx.x << 7;

    // A tile loader: 128 rows x 8 cols, 4 floats/thread
    const int arow = tid >> 1;
    const int acol = (tid & 1) << 2;
    const float* aptr = A + crow(m0 + arow) + acol;

    // B tile loader: 8 rows x 128 cols, 4 floats/thread
    const int brow = tid >> 5;
    const int bcol = (tid & 31) << 2;
    const float* bptr = W + (size_t)brow * N + n0 + bcol;

    const int tx = tid & 15;
    const int ty = tid >> 4;

    ull acc[8][4];
#pragma unroll
    for (int i = 0; i < 8; i++)
#pragma unroll
        for (int j = 0; j < 4; j++) acc[i][j] = 0ull;

    float4 aR = *(const float4*)(aptr);
    float4 bR = *(const float4*)(bptr);

    for (int kt = 0; kt < K; kt += 8) {
        As[acol + 0][arow] = aR.x;
        As[acol + 1][arow] = aR.y;
        As[acol + 2][arow] = aR.z;
        As[acol + 3][arow] = aR.w;
        *(float4*)&Bs[brow][bcol] = bR;
        __syncthreads();

        if (kt + 8 < K) {
            aR = *(const float4*)(aptr + kt + 8);
            bR = *(const float4*)(bptr + (size_t)(kt + 8) * N);
        }

#pragma unroll
        for (int kk = 0; kk < 8; kk++) {
            const float4 a0 = *(const float4*)&As[kk][(ty << 2)];
            const float4 a1 = *(const float4*)&As[kk][64 + (ty << 2)];
            const ulonglong2 b0 = *(const ulonglong2*)&Bs[kk][(tx << 2)];
            const ulonglong2 b1 = *(const ulonglong2*)&Bs[kk][64 + (tx << 2)];
            ull bv0 = b0.x, bv1 = b0.y, bv2 = b1.x, bv3 = b1.y;
            float av[8] = {a0.x, a0.y, a0.z, a0.w, a1.x, a1.y, a1.z, a1.w};
#pragma unroll
            for (int i = 0; i < 8; i++) {
                ull ai = f2_pack(av[i], av[i]);
                acc[i][0] = f2_fma(ai, bv0, acc[i][0]);
                acc[i][1] = f2_fma(ai, bv1, acc[i][1]);
                acc[i][2] = f2_fma(ai, bv2, acc[i][2]);
                acc[i][3] = f2_fma(ai, bv3, acc[i][3]);
            }
        }
        __syncthreads();
    }

    const float4 bb0 = *(const float4*)&bias[n0 + (tx << 2)];
    const float4 bb1 = *(const float4*)&bias[n0 + 64 + (tx << 2)];

#pragma unroll
    for (int i = 0; i < 8; i++) {
        const int rloc = (i < 4) ? ((ty << 2) + i) : (64 + (ty << 2) + (i - 4));
        const int r = m0 + rloc;
        const size_t co = CMAP ? crow(r) : (size_t)r * N;
        float4 v0, v1;
        f2_unpack(acc[i][0], v0.x, v0.y);
        f2_unpack(acc[i][1], v0.z, v0.w);
        f2_unpack(acc[i][2], v1.x, v1.y);
        f2_unpack(acc[i][3], v1.z, v1.w);
        v0.x += bb0.x; v0.y += bb0.y; v0.z += bb0.z; v0.w += bb0.w;
        v1.x += bb1.x; v1.y += bb1.y; v1.z += bb1.z; v1.w += bb1.w;
        if (RELU) {
            v0.x = fmaxf(v0.x, 0.f); v0.y = fmaxf(v0.y, 0.f);
            v0.z = fmaxf(v0.z, 0.f); v0.w = fmaxf(v0.w, 0.f);
            v1.x = fmaxf(v1.x, 0.f); v1.y = fmaxf(v1.y, 0.f);
            v1.z = fmaxf(v1.z, 0.f); v1.w = fmaxf(v1.w, 0.f);
        }
        *(float4*)&C[co + n0 + (tx << 2)]      = v0;
        *(float4*)&C[co + n0 + 64 + (tx << 2)] = v1;
    }
}

// ------------- highway elementwise: x = g*x + (1-g)*relu(nl) -------------
// xint: conv-mapped interior base (in-place). proj [M,1024] plain.
// outp (nullable): plain [M,1024] row-stride output (pre-offset for b-half).
__global__ void highway_ew(float* __restrict__ xint, const float* __restrict__ proj,
                           float* __restrict__ outp)
{
    const int idx = blockIdx.x * 256 + threadIdx.x;
    const int e = idx << 2;                 // element index into [M, 512]
    const int r = e >> 9;
    const int h = e & 511;
    const float4 nl = *(const float4*)&proj[(size_t)r * 1024 + h];
    const float4 gt = *(const float4*)&proj[(size_t)r * 1024 + 512 + h];
    const size_t xo = crow(r) + h;
    const float4 x = *(const float4*)&xint[xo];
    float4 o;
    {
        float g = 1.0f / (1.0f + __expf(-gt.x));
        o.x = g * x.x + (1.0f - g) * fmaxf(nl.x, 0.0f);
    }
    {
        float g = 1.0f / (1.0f + __expf(-gt.y));
        o.y = g * x.y + (1.0f - g) * fmaxf(nl.y, 0.0f);
    }
    {
        float g = 1.0f / (1.0f + __expf(-gt.z));
        o.z = g * x.z + (1.0f - g) * fmaxf(nl.z, 0.0f);
    }
    {
        float g = 1.0f / (1.0f + __expf(-gt.w));
        o.w = g * x.w + (1.0f - g) * fmaxf(nl.w, 0.0f);
    }
    *(float4*)&xint[xo] = o;
    if (outp) *(float4*)&outp[(size_t)r * 1024 + h] = o;
}

// ------------- fill pad rows (front = fwd_pads[i], back = bwd_pads[i]) ----
__global__ void fill_pads(float* __restrict__ pad, const float* __restrict__ fp,
                          const float* __restrict__ bp)
{
    const int idx = blockIdx.x * 256 + threadIdx.x;   // B*8*512/4 = 32768 threads
    const int e = idx << 2;
    const int b = e >> 12;       // 8*512 floats per batch
    const int rem = e & 4095;
    const int p = rem >> 9;
    const int h = rem & 511;
    float4 v;
    size_t drow;
    if (p < 4) {
        v = *(const float4*)&fp[p * Hd + h];
        drow = (size_t)(b * SPd + p);
    } else {
        v = *(const float4*)&bp[(p - 4) * Hd + h];
        drow = (size_t)(b * SPd + Wd + Ss + (p - 4));
    }
    *(float4*)&pad[drow * Hd + h] = v;
}

// ------------- copy inputs into both layer-0 padded interiors -------------
__global__ void init_copy(const float* __restrict__ in,
                          float* __restrict__ d0, float* __restrict__ d1)
{
    const int idx = blockIdx.x * 256 + threadIdx.x;
    const int e = idx << 2;
    const int r = e >> 9;
    const int h = e & 511;
    const float4 v = *(const float4*)&in[e];
    const size_t o = crow(r) + h;
    *(float4*)&d0[o] = v;
    *(float4*)&d1[o] = v;
}

extern "C" void kernel_launch(void* const* d_in, const int* in_sizes, int n_in,
                              void* d_out, int out_size)
{
    const float* inputs   = (const float*)d_in[0];
    // d_in[1] = mask (unused by reference math: mask is all ones)
    const float* fwd_pads = (const float*)d_in[2];
    const float* bwd_pads = (const float*)d_in[3];
    const float* fwd_W    = (const float*)d_in[4];
    const float* fwd_bi   = (const float*)d_in[5];
    const float* bwd_W    = (const float*)d_in[6];
    const float* bwd_bi   = (const float*)d_in[7];
    const float* fwd_hw_W = (const float*)d_in[8];
    const float* fwd_hw_b = (const float*)d_in[9];
    const float* bwd_hw_W = (const float*)d_in[10];
    const float* bwd_hw_b = (const float*)d_in[11];
    float* out = (float*)d_out;

    float *pf0, *pb0, *tmp;
    cudaGetSymbolAddress((void**)&pf0, g_pad_f);
    cudaGetSymbolAddress((void**)&pb0, g_pad_b);
    cudaGetSymbolAddress((void**)&tmp, g_tmp);
    float* pf[2] = { pf0, pf0 + (size_t)Bb * SPd * Hd };
    float* pb[2] = { pb0, pb0 + (size_t)Bb * SPd * Hd };

    const size_t INT_OFF = (size_t)Wd * Hd;   // interior offset within padded buf

    init_copy<<<8192, 256>>>(inputs, pf[0] + INT_OFF, pb[0] + INT_OFF);

    for (int i = 0; i < LLd; i++) {
        const int cur = i & 1;
        const int nxt = cur ^ 1;
        const float* fp = fwd_pads + (size_t)i * Wd * Hd;
        const float* bp = bwd_pads + (size_t)i * Wd * Hd;

        fill_pads<<<128, 256>>>(pf[cur], fp, bp);
        fill_pads<<<128, 256>>>(pb[cur], fp, bp);

        // conv GEMMs: [16384, 2560] @ [2560, 512], relu+bias, write next interior
        dim3 gc(512 / 128, MT / 128);
        gemm_k<CINd, true, true><<<gc, 256>>>(
            pf[cur], fwd_W + (size_t)i * CINd * Hd, fwd_bi + (size_t)i * Hd,
            pf[nxt] + INT_OFF, 512);
        gemm_k<CINd, true, true><<<gc, 256>>>(
            pb[cur] + INT_OFF, bwd_W + (size_t)i * CINd * Hd, bwd_bi + (size_t)i * Hd,
            pb[nxt] + INT_OFF, 512);

        // highway: 2x (GEMM [16384,512]@[512,1024] + gated combine), per direction
        dim3 gh(1024 / 128, MT / 128);
        for (int j = 0; j < 2; j++) {
            gemm_k<Hd, false, false><<<gh, 256>>>(
                pf[nxt] + INT_OFF,
                fwd_hw_W + ((size_t)i * 2 + j) * Hd * 2 * Hd,
                fwd_hw_b + ((size_t)i * 2 + j) * 2 * Hd,
                tmp, 1024);
            highway_ew<<<8192, 256>>>(
                pf[nxt] + INT_OFF, tmp,
                (j == 1) ? (out + (size_t)i * MT * 1024) : nullptr);
        }
        for (int j = 0; j < 2; j++) {
            gemm_k<Hd, false, false><<<gh, 256>>>(
                pb[nxt] + INT_OFF,
                bwd_hw_W + ((size_t)i * 2 + j) * Hd * 2 * Hd,
                bwd_hw_b + ((size_t)i * 2 + j) * 2 * Hd,
                tmp, 1024);
            highway_ew<<<8192, 256>>>(
                pb[nxt] + INT_OFF, tmp,
                (j == 1) ? (out + (size_t)i * MT * 1024 + 512) : nullptr);
        }
    }
}

// round 4
// speedup vs baseline: 3.5297x; 3.5297x over previous
#include <cuda_runtime.h>
#include <cuda_bf16.h>
#include <cstdint>

typedef unsigned int u32;
typedef unsigned long long u64;
typedef __nv_bfloat16  bf16;
typedef __nv_bfloat162 bf162;

#define Hd   512
#define SPd  520
#define MTr  16384
#define PSZ  (32*SPd*Hd)
#define INTOFF 2048
#define CWL  (512*2560)
#define HWL  (1024*512)

// ---------------- static device scratch ----------------
__device__ bf16 g_pf[2][2][PSZ];      // fwd padded activations [buf][split h/m]
__device__ bf16 g_pb[2][2][PSZ];      // bwd
__device__ bf16 g_cW[2][2][3*CWL];    // conv weights [dir][split][layer][512 n][2560 k]
__device__ bf16 g_hW[2][2][6*HWL];    // hw weights   [dir][split][l*2+j][1024 q][512 k]

// ---------------- helpers ----------------
__device__ __forceinline__ u32 s2u(const void* p) {
    u32 a; asm("{ .reg .u64 t; cvta.to.shared.u64 t, %1; cvt.u32.u64 %0, t; }"
               : "=r"(a) : "l"(p)); return a;
}
__device__ __forceinline__ void cp16(u32 d, const void* s) {
    asm volatile("cp.async.cg.shared.global [%0], [%1], 16;" :: "r"(d), "l"(s) : "memory");
}
__device__ __forceinline__ void ldsm4(u32* r, u32 a) {
    asm volatile("ldmatrix.sync.aligned.m8n8.x4.shared.b16 {%0,%1,%2,%3}, [%4];"
                 : "=r"(r[0]), "=r"(r[1]), "=r"(r[2]), "=r"(r[3]) : "r"(a));
}
__device__ __forceinline__ void mma16816(float* d, const u32* a, const u32* b) {
    asm volatile("mma.sync.aligned.m16n8k16.row.col.f32.bf16.bf16.f32 "
                 "{%0,%1,%2,%3}, {%4,%5,%6,%7}, {%8,%9}, {%0,%1,%2,%3};"
                 : "+f"(d[0]), "+f"(d[1]), "+f"(d[2]), "+f"(d[3])
                 : "r"(a[0]), "r"(a[1]), "r"(a[2]), "r"(a[3]), "r"(b[0]), "r"(b[1]));
}

__device__ __forceinline__ size_t crow(int r) {
    return (size_t)(r + ((r >> 9) << 3)) * Hd;   // conv-mapped padded row
}
__device__ __forceinline__ void split2(float v0, float v1, u32& hh, u32& mm) {
    bf162 h2 = __float22bfloat162_rn(make_float2(v0, v1));
    float2 hf = __bfloat1622float2(h2);
    bf162 m2 = __float22bfloat162_rn(make_float2(v0 - hf.x, v1 - hf.y));
    hh = *(u32*)&h2; mm = *(u32*)&m2;
}
__device__ __forceinline__ u32 swz(int row, int ch) {   // 64B-row XOR swizzle
    return (u32)(row * 64 + ((ch ^ ((row >> 1) & 3)) << 4));
}

#define STAGE 32768
#define NSTG  4
#define SSTG_OFF (NSTG*STAGE)
#define DSM   (128 + NSTG*STAGE + 128*132*4)

// ================= split-bf16 HMMA GEMM + fused epilogue =================
// C[128, 128-per-CTA] = sum_k A[m][k]*Wt[n][k], 3 split passes.
// MODE 0: conv  -> relu(D+bias), split-store to Yh/Ym (conv-mapped, width 512)
// MODE 1: hw    -> gated combine with X, split-store
// MODE 2: hw    -> same + fp32 store to outp
template<int K, int MODE>
__global__ __launch_bounds__(256, 1)
void mma_gemm(const bf16* __restrict__ Ah, const bf16* __restrict__ Am,
              const bf16* __restrict__ Wh, const bf16* __restrict__ Wm,
              const float* __restrict__ bias,
              const bf16* __restrict__ Xh, const bf16* __restrict__ Xm,
              bf16* __restrict__ Yh, bf16* __restrict__ Ym,
              float* __restrict__ outp)
{
    constexpr int NC = K / 32;
    extern __shared__ char dsm[];
    const u32 base = (s2u(dsm) + 127) & ~127u;
    const u32 pad  = base - s2u(dsm);
    float* sstg = (float*)(dsm + pad + SSTG_OFF);

    const int tid  = threadIdx.x;
    const int lane = tid & 31;
    const int wid  = tid >> 5;
    const int wm   = (wid >> 2) * 64;
    const int wn   = (wid & 3) * 32;
    const int m0   = blockIdx.y << 7;
    const int nb0  = blockIdx.x << 7;

    // Precompute per-thread load sources/dests (4 A + 4 B transfers/stage)
    const bf16* aSrc[4]; const bf16* bSrc[4]; u32 aDst[4], bDst[4];
#pragma unroll
    for (int it = 0; it < 4; it++) {
        int v = tid + it * 256;             // 0..1023
        int pl = v >> 9, rem = v & 511;
        int row = rem >> 2, ch = rem & 3;
        aSrc[it] = (pl ? Am : Ah) + crow(m0 + row) + ch * 8;
        aDst[it] = base + pl * 8192 + swz(row, ch);
        bSrc[it] = (pl ? Wm : Wh) + (size_t)(nb0 + row) * K + ch * 8;
        bDst[it] = base + 16384 + pl * 8192 + swz(row, ch);
    }

    auto load_chunk = [&](int c) {
        const u32 so = (u32)((c & 3) * STAGE);
        const int kc = c * 32;
#pragma unroll
        for (int it = 0; it < 4; it++) cp16(aDst[it] + so, aSrc[it] + kc);
#pragma unroll
        for (int it = 0; it < 4; it++) cp16(bDst[it] + so, bSrc[it] + kc);
        asm volatile("cp.async.commit_group;" ::: "memory");
    };

    float acc[4][4][4];
#pragma unroll
    for (int i = 0; i < 4; i++)
#pragma unroll
        for (int j = 0; j < 4; j++)
#pragma unroll
            for (int q = 0; q < 4; q++) acc[i][j][q] = 0.f;

    load_chunk(0); load_chunk(1); load_chunk(2);

    // Precompute fragment smem addresses (chunk-invariant parts)
    const int ar = lane & 15;                 // A row within tile
    const int ac = lane >> 4;                 // A k-chunk half
    const int br = (lane & 7) + ((lane & 16) >> 1);
    const int bc = (lane >> 3) & 1;

    for (int c = 0; c < NC; c++) {
        asm volatile("cp.async.wait_group 2;" ::: "memory");
        __syncthreads();
        if (c + 3 < NC) load_chunk(c + 3);
        else            asm volatile("cp.async.commit_group;" ::: "memory");

        const u32 sb = base + (u32)((c & 3) * STAGE);
#pragma unroll
        for (int s = 0; s < 2; s++) {
            u32 a[2][4][4], bfb[2][8];
#pragma unroll
            for (int pl = 0; pl < 2; pl++) {
#pragma unroll
                for (int i = 0; i < 4; i++) {
                    int row = wm + i * 16 + ar;
                    ldsm4(a[pl][i], sb + pl * 8192 + swz(row, 2 * s + ac));
                }
#pragma unroll
                for (int jp = 0; jp < 2; jp++) {
                    int row = wn + jp * 16 + br;
                    ldsm4(&bfb[pl][jp * 4], sb + 16384 + pl * 8192 + swz(row, 2 * s + bc));
                }
            }
#pragma unroll
            for (int i = 0; i < 4; i++)
#pragma unroll
                for (int j = 0; j < 4; j++) {
                    mma16816(acc[i][j], a[0][i], &bfb[0][j * 2]);  // Ah*Bh
                    mma16816(acc[i][j], a[0][i], &bfb[1][j * 2]);  // Ah*Bm
                    mma16816(acc[i][j], a[1][i], &bfb[0][j * 2]);  // Am*Bh
                }
        }
    }

    // ---- stage accumulators to smem ----
#pragma unroll
    for (int i = 0; i < 4; i++)
#pragma unroll
        for (int j = 0; j < 4; j++) {
            int r0 = wm + i * 16 + (lane >> 2);
            int cc = wn + j * 8 + (lane & 3) * 2;
            *(float2*)&sstg[r0 * 132 + cc]       = make_float2(acc[i][j][0], acc[i][j][1]);
            *(float2*)&sstg[(r0 + 8) * 132 + cc] = make_float2(acc[i][j][2], acc[i][j][3]);
        }
    __syncthreads();

    // ---- fused epilogue ----
    const int r  = tid >> 1;
    const int gr = m0 + r;

    if (MODE == 0) {
        const int c0 = (tid & 1) * 64;
#pragma unroll
        for (int c8 = 0; c8 < 8; c8++) {
            const int cb = c0 + c8 * 8;
            u32 hh[4], mm[4];
#pragma unroll
            for (int t = 0; t < 4; t++) {
                float v0 = fmaxf(sstg[r * 132 + cb + 2*t]     + bias[nb0 + cb + 2*t],     0.f);
                float v1 = fmaxf(sstg[r * 132 + cb + 2*t + 1] + bias[nb0 + cb + 2*t + 1], 0.f);
                split2(v0, v1, hh[t], mm[t]);
            }
            const size_t o = crow(gr) + nb0 + cb;
            *(uint4*)(Yh + o) = *(uint4*)hh;
            *(uint4*)(Ym + o) = *(uint4*)mm;
        }
    } else {
        const int fbase = blockIdx.x * 64;
        const int fl0   = (tid & 1) * 32;
#pragma unroll
        for (int c8 = 0; c8 < 4; c8++) {
            const int fl = fl0 + c8 * 8;
            const int f  = fbase + fl;
            uint4 xh4 = *(const uint4*)(Xh + crow(gr) + f);
            uint4 xm4 = *(const uint4*)(Xm + crow(gr) + f);
            u32 hh[4], mm[4];
            float ov[8];
#pragma unroll
            for (int t = 0; t < 4; t++) {
                float2 xh2 = __bfloat1622float2(*(bf162*)&((u32*)&xh4)[t]);
                float2 xm2 = __bfloat1622float2(*(bf162*)&((u32*)&xm4)[t]);
                float x0 = xh2.x + xm2.x, x1 = xh2.y + xm2.y;
                float nl0 = sstg[r * 132 + fl + 2*t]       + bias[f + 2*t];
                float nl1 = sstg[r * 132 + fl + 2*t + 1]   + bias[f + 2*t + 1];
                float gt0 = sstg[r * 132 + 64 + fl + 2*t]     + bias[512 + f + 2*t];
                float gt1 = sstg[r * 132 + 64 + fl + 2*t + 1] + bias[512 + f + 2*t + 1];
                float s0 = 1.f / (1.f + __expf(-gt0));
                float s1 = 1.f / (1.f + __expf(-gt1));
                float o0 = s0 * x0 + (1.f - s0) * fmaxf(nl0, 0.f);
                float o1 = s1 * x1 + (1.f - s1) * fmaxf(nl1, 0.f);
                split2(o0, o1, hh[t], mm[t]);
                ov[2*t] = o0; ov[2*t + 1] = o1;
            }
            const size_t yo = crow(gr) + f;
            *(uint4*)(Yh + yo) = *(uint4*)hh;
            *(uint4*)(Ym + yo) = *(uint4*)mm;
            if (MODE == 2) {
                *(float4*)(outp + (size_t)gr * 1024 + f)     = *(float4*)&ov[0];
                *(float4*)(outp + (size_t)gr * 1024 + f + 4) = *(float4*)&ov[4];
            }
        }
    }
}

// ================= prep kernels =================
__global__ void prep_convW(const float* __restrict__ W, bf16* __restrict__ Oh, bf16* __restrict__ Om) {
    // W: [3][2560][512] -> O: [3][512 n][2560 k]
    int w = (blockIdx.x * blockDim.x + threadIdx.x) >> 5;
    int lane = threadIdx.x & 31;
    int layer = w / (16 * 320); int rem = w % (16 * 320);
    int n = (rem / 320) * 32 + lane; int k0 = (rem % 320) * 8;
    const float* src = W + (size_t)layer * 2560 * 512 + (size_t)k0 * 512 + n;
    u32 hh[4], mm[4];
#pragma unroll
    for (int t = 0; t < 4; t++)
        split2(src[(2*t) * 512], src[(2*t + 1) * 512], hh[t], mm[t]);
    size_t o = ((size_t)layer * 512 + n) * 2560 + k0;
    *(uint4*)(Oh + o) = *(uint4*)hh;
    *(uint4*)(Om + o) = *(uint4*)mm;
}

__global__ void prep_hwW(const float* __restrict__ W, bf16* __restrict__ Oh, bf16* __restrict__ Om) {
    // W: [6][512][1024] -> O: [6][1024 q][512 k]
    // q layout: block fb (0..7) covers cols [fb*128, fb*128+128):
    //   cols 0-63  = nl  features fb*64..fb*64+63
    //   cols 64-127= gate features fb*64..fb*64+63
    int w = (blockIdx.x * blockDim.x + threadIdx.x) >> 5;
    int lane = threadIdx.x & 31;
    int lw = w / (32 * 64); int rem = w % (32 * 64);
    int np = (rem / 64) * 32 + lane; int k0 = (rem % 64) * 8;
    int f = (np < 512) ? np : (np - 512);
    int q = (f >> 6) * 128 + ((np < 512) ? (f & 63) : (64 + (f & 63)));
    const float* src = W + (size_t)lw * 512 * 1024 + (size_t)k0 * 1024 + np;
    u32 hh[4], mm[4];
#pragma unroll
    for (int t = 0; t < 4; t++)
        split2(src[(2*t) * 1024], src[(2*t + 1) * 1024], hh[t], mm[t]);
    size_t o = ((size_t)lw * 1024 + q) * 512 + k0;
    *(uint4*)(Oh + o) = *(uint4*)hh;
    *(uint4*)(Om + o) = *(uint4*)mm;
}

__global__ void prep_act(const float* __restrict__ in,
                         bf16* __restrict__ fh, bf16* __restrict__ fm,
                         bf16* __restrict__ bh, bf16* __restrict__ bm) {
    int idx = blockIdx.x * 256 + threadIdx.x;
    int e = idx << 2;
    int r = e >> 9, h = e & 511;
    float4 v = *(const float4*)(in + e);
    u32 hw2[2], mw2[2];
    split2(v.x, v.y, hw2[0], mw2[0]);
    split2(v.z, v.w, hw2[1], mw2[1]);
    size_t o = crow(r) + h;
    *(uint2*)(fh + o) = *(uint2*)hw2; *(uint2*)(fm + o) = *(uint2*)mw2;
    *(uint2*)(bh + o) = *(uint2*)hw2; *(uint2*)(bm + o) = *(uint2*)mw2;
}

__global__ void prep_pads(const float* __restrict__ fp, const float* __restrict__ bp,
                          bf16* __restrict__ fh, bf16* __restrict__ fm,
                          bf16* __restrict__ bh, bf16* __restrict__ bm) {
    int idx = blockIdx.x * 256 + threadIdx.x;
    int e = idx << 2;
    int b = e >> 12; int rem = e & 4095; int p = rem >> 9; int h = rem & 511;
    const float* s = (p < 4) ? (fp + p * 512 + h) : (bp + (p - 4) * 512 + h);
    int row = (p < 4) ? (b * 520 + p) : (b * 520 + 516 + (p - 4));
    float4 v = *(const float4*)s;
    u32 hw2[2], mw2[2];
    split2(v.x, v.y, hw2[0], mw2[0]);
    split2(v.z, v.w, hw2[1], mw2[1]);
    size_t o = (size_t)row * 512 + h;
    *(uint2*)(fh + o) = *(uint2*)hw2; *(uint2*)(fm + o) = *(uint2*)mw2;
    *(uint2*)(bh + o) = *(uint2*)hw2; *(uint2*)(bm + o) = *(uint2*)mw2;
}

// ================= host =================
extern "C" void kernel_launch(void* const* d_in, const int* in_sizes, int n_in,
                              void* d_out, int out_size)
{
    const float* inputs   = (const float*)d_in[0];
    const float* fwd_pads = (const float*)d_in[2];
    const float* bwd_pads = (const float*)d_in[3];
    const float* fwd_W    = (const float*)d_in[4];
    const float* fwd_bi   = (const float*)d_in[5];
    const float* bwd_W    = (const float*)d_in[6];
    const float* bwd_bi   = (const float*)d_in[7];
    const float* fwd_hw_W = (const float*)d_in[8];
    const float* fwd_hw_b = (const float*)d_in[9];
    const float* bwd_hw_W = (const float*)d_in[10];
    const float* bwd_hw_b = (const float*)d_in[11];
    float* out = (float*)d_out;

    bf16 *pfB, *pbB, *cwB, *hwB;
    cudaGetSymbolAddress((void**)&pfB, g_pf);
    cudaGetSymbolAddress((void**)&pbB, g_pb);
    cudaGetSymbolAddress((void**)&cwB, g_cW);
    cudaGetSymbolAddress((void**)&hwB, g_hW);
    bf16 *pfh[2] = { pfB,                 pfB + 2*(size_t)PSZ };
    bf16 *pfm[2] = { pfB + PSZ,           pfB + 3*(size_t)PSZ };
    bf16 *pbh[2] = { pbB,                 pbB + 2*(size_t)PSZ };
    bf16 *pbm[2] = { pbB + PSZ,           pbB + 3*(size_t)PSZ };
    bf16 *cwh[2] = { cwB,                 cwB + 2*(size_t)(3*CWL) };
    bf16 *cwm[2] = { cwB + 3*(size_t)CWL, cwB + 3*(size_t)(3*CWL) };
    bf16 *hwh[2] = { hwB,                 hwB + 2*(size_t)(6*HWL) };
    bf16 *hwm[2] = { hwB + 6*(size_t)HWL, hwB + 3*(size_t)(6*HWL) };

    static int inited = 0;
    if (!inited) {
        cudaFuncSetAttribute(mma_gemm<2560,0>, cudaFuncAttributeMaxDynamicSharedMemorySize, DSM);
        cudaFuncSetAttribute(mma_gemm<512,1>,  cudaFuncAttributeMaxDynamicSharedMemorySize, DSM);
        cudaFuncSetAttribute(mma_gemm<512,2>,  cudaFuncAttributeMaxDynamicSharedMemorySize, DSM);
        inited = 1;
    }

    prep_convW<<<1920, 256>>>(fwd_W, cwh[0], cwm[0]);
    prep_convW<<<1920, 256>>>(bwd_W, cwh[1], cwm[1]);
    prep_hwW<<<1536, 256>>>(fwd_hw_W, hwh[0], hwm[0]);
    prep_hwW<<<1536, 256>>>(bwd_hw_W, hwh[1], hwm[1]);
    prep_act<<<8192, 256>>>(inputs, pfh[0] + INTOFF, pfm[0] + INTOFF,
                                    pbh[0] + INTOFF, pbm[0] + INTOFF);

    int c = 0;
    for (int l = 0; l < 3; l++) {
        const int d = 1 - c;
        prep_pads<<<128, 256>>>(fwd_pads + (size_t)l * 2048, bwd_pads + (size_t)l * 2048,
                                pfh[c], pfm[c], pbh[c], pbm[c]);

        // conv: buf[c] (padded) -> buf[d] interior, relu+bias
        mma_gemm<2560,0><<<dim3(4,128), 256, DSM>>>(
            pfh[c], pfm[c], cwh[0] + (size_t)l*CWL, cwm[0] + (size_t)l*CWL,
            fwd_bi + (size_t)l*512, nullptr, nullptr,
            pfh[d] + INTOFF, pfm[d] + INTOFF, nullptr);
        mma_gemm<2560,0><<<dim3(4,128), 256, DSM>>>(
            pbh[c] + 2048, pbm[c] + 2048, cwh[1] + (size_t)l*CWL, cwm[1] + (size_t)l*CWL,
            bwd_bi + (size_t)l*512, nullptr, nullptr,
            pbh[d] + INTOFF, pbm[d] + INTOFF, nullptr);

        // hw1: buf[d] -> buf[c]
        mma_gemm<512,1><<<dim3(8,128), 256, DSM>>>(
            pfh[d] + INTOFF, pfm[d] + INTOFF,
            hwh[0] + (size_t)(l*2)*HWL, hwm[0] + (size_t)(l*2)*HWL,
            fwd_hw_b + (size_t)(l*2)*1024,
            pfh[d] + INTOFF, pfm[d] + INTOFF,
            pfh[c] + INTOFF, pfm[c] + INTOFF, nullptr);
        mma_gemm<512,1><<<dim3(8,128), 256, DSM>>>(
            pbh[d] + INTOFF, pbm[d] + INTOFF,
            hwh[1] + (size_t)(l*2)*HWL, hwm[1] + (size_t)(l*2)*HWL,
            bwd_hw_b + (size_t)(l*2)*1024,
            pbh[d] + INTOFF, pbm[d] + INTOFF,
            pbh[c] + INTOFF, pbm[c] + INTOFF, nullptr);

        // hw2: buf[c] -> buf[d], + fp32 output
        mma_gemm<512,2><<<dim3(8,128), 256, DSM>>>(
            pfh[c] + INTOFF, pfm[c] + INTOFF,
            hwh[0] + (size_t)(l*2+1)*HWL, hwm[0] + (size_t)(l*2+1)*HWL,
            fwd_hw_b + (size_t)(l*2+1)*1024,
            pfh[c] + INTOFF, pfm[c] + INTOFF,
            pfh[d] + INTOFF, pfm[d] + INTOFF,
            out + (size_t)l * MTr * 1024);
        mma_gemm<512,2><<<dim3(8,128), 256, DSM>>>(
            pbh[c] + INTOFF, pbm[c] + INTOFF,
            hwh[1] + (size_t)(l*2+1)*HWL, hwm[1] + (size_t)(l*2+1)*HWL,
            bwd_hw_b + (size_t)(l*2+1)*1024,
            pbh[c] + INTOFF, pbm[c] + INTOFF,
            pbh[d] + INTOFF, pbm[d] + INTOFF,
            out + (size_t)l * MTr * 1024 + 512);

        c = d;
    }
}